// round 5
// baseline (speedup 1.0000x reference)
#include <cuda_runtime.h>
#include <cuda_fp16.h>
#include <math.h>

#define NN 50000
#define NE 800000
#define DD 64
#define NR 500
#define NT 1000

// ---- scratch (no allocs allowed) ----
__device__ float  g_ex[NE];
__device__ float  g_den[NN];
__device__ float  g_agg[NN * DD];
__device__ float  g_hatt[NN];
__device__ float  g_tatt[NN];
__device__ float  g_ratt[NR];
__device__ float  g_tsatt[NT];
__device__ int4   g_pidx[NE];          // {src, dst, etype, etime}
__device__ __half g_xh[NN * DD];       // fp16 copies for the gather-heavy pass
__device__ __half g_rh[NR * DD];
__device__ __half g_th[NT * DD];

// ---------------------------------------------------------------------------
// Fused: zero agg/den + per-row scalar attention projections (warp per row)
// + write fp16 copies of x / rel / time rows (free: rows already loaded).
// ---------------------------------------------------------------------------
__global__ void k_scalar(const float* __restrict__ x,
                         const float* __restrict__ rel,
                         const float* __restrict__ tm,
                         const float* __restrict__ ah,
                         const float* __restrict__ at,
                         const float* __restrict__ ar,
                         const float* __restrict__ ats) {
    int gtid = blockIdx.x * blockDim.x + threadIdx.x;
    int stride = gridDim.x * blockDim.x;
    for (int j = gtid; j < NN * DD; j += stride) g_agg[j] = 0.f;
    for (int j = gtid; j < NN; j += stride) g_den[j] = 0.f;

    int w = gtid >> 5;
    int lane = threadIdx.x & 31;
    if (w < NN) {
        const float* row = x + (size_t)w * DD;
        float v0 = row[lane], v1 = row[lane + 32];
        g_xh[(size_t)w * DD + lane]      = __float2half(v0);
        g_xh[(size_t)w * DD + lane + 32] = __float2half(v1);
        float h = v0 * ah[lane] + v1 * ah[lane + 32];
        float t = v0 * at[lane] + v1 * at[lane + 32];
#pragma unroll
        for (int o = 16; o; o >>= 1) {
            h += __shfl_xor_sync(0xffffffffu, h, o);
            t += __shfl_xor_sync(0xffffffffu, t, o);
        }
        if (lane == 0) { g_hatt[w] = h; g_tatt[w] = t; }
    } else if (w < NN + NR) {
        int r = w - NN;
        const float* row = rel + (size_t)r * DD;
        float v0 = row[lane], v1 = row[lane + 32];
        g_rh[(size_t)r * DD + lane]      = __float2half(v0);
        g_rh[(size_t)r * DD + lane + 32] = __float2half(v1);
        float s = v0 * ar[lane] + v1 * ar[lane + 32];
#pragma unroll
        for (int o = 16; o; o >>= 1) s += __shfl_xor_sync(0xffffffffu, s, o);
        if (lane == 0) g_ratt[r] = s;
    } else if (w < NN + NR + NT) {
        int t = w - NN - NR;
        const float* row = tm + (size_t)t * DD;
        float v0 = row[lane], v1 = row[lane + 32];
        g_th[(size_t)t * DD + lane]      = __float2half(v0);
        g_th[(size_t)t * DD + lane + 32] = __float2half(v1);
        float s = v0 * ats[lane] + v1 * ats[lane + 32];
#pragma unroll
        for (int o = 16; o; o >>= 1) s += __shfl_xor_sync(0xffffffffu, s, o);
        if (lane == 0) g_tsatt[t] = s;
    }
}

// ---------------------------------------------------------------------------
// Edge pass 1: ex = exp(leaky_relu(logit)); den[dst] += ex; pack indices.
// ---------------------------------------------------------------------------
__global__ void k_edge1(const int* __restrict__ src, const int* __restrict__ dst,
                        const int* __restrict__ ety, const int* __restrict__ eti) {
    int i = blockIdx.x * blockDim.x + threadIdx.x;
    if (i >= NE) return;
    int s = src[i], d = dst[i], r = ety[i], t = eti[i];
    g_pidx[i] = make_int4(s, d, r, t);
    float e = g_hatt[s] - g_tatt[d] + g_ratt[r] + g_tsatt[t];
    e = (e > 0.f) ? e : 0.1f * e;
    float ex = __expf(e);
    g_ex[i] = ex;
    atomicAdd(&g_den[d], ex);
}

// ---------------------------------------------------------------------------
// Edge pass 2 (dominant): 8 threads/edge; each lane loads 16B (8 fp16 cols)
// per matrix -> 3 gather wavefronts/edge (was 6 in fp32).
// agg[dst] += att * (x[src]+t) * (rel+t)   via red.global.add.v4.f32
// ---------------------------------------------------------------------------
__global__ void k_edge2() {
    int gt = blockIdx.x * blockDim.x + threadIdx.x;
    int i = gt >> 3;
    if (i >= NE) return;
    int sub = gt & 7;
    int c = sub * 8;               // 8 contiguous cols per lane

    int4 p = __ldg(&g_pidx[i]);    // broadcast across the 8-lane group

    float att = 0.f;
    if (sub == 0) att = __fdividef(__ldg(&g_ex[i]), __ldg(&g_den[p.y]));
    att = __shfl_sync(0xffffffffu, att, (threadIdx.x & 31) & ~7);

    uint4 xu = *(const uint4*)(g_xh + (size_t)p.x * DD + c);
    uint4 ru = *(const uint4*)(g_rh + (size_t)p.z * DD + c);
    uint4 tu = *(const uint4*)(g_th + (size_t)p.w * DD + c);

    float o[8];
#pragma unroll
    for (int j = 0; j < 4; j++) {
        __half2 xh = *reinterpret_cast<__half2*>(&(&xu.x)[j]);
        __half2 rh = *reinterpret_cast<__half2*>(&(&ru.x)[j]);
        __half2 th = *reinterpret_cast<__half2*>(&(&tu.x)[j]);
        float2 xf = __half22float2(xh);
        float2 rf = __half22float2(rh);
        float2 tf = __half22float2(th);
        o[j * 2]     = (xf.x + tf.x) * (rf.x + tf.x) * att;
        o[j * 2 + 1] = (xf.y + tf.y) * (rf.y + tf.y) * att;
    }

    float* pd = &g_agg[(size_t)p.y * DD + c];
    asm volatile("red.global.add.v4.f32 [%0], {%1,%2,%3,%4};"
                 :: "l"(pd), "f"(o[0]), "f"(o[1]), "f"(o[2]), "f"(o[3])
                 : "memory");
    asm volatile("red.global.add.v4.f32 [%0], {%1,%2,%3,%4};"
                 :: "l"(pd + 4), "f"(o[4]), "f"(o[5]), "f"(o[6]), "f"(o[7])
                 : "memory");
}

// ---------------------------------------------------------------------------
// Fused: x_out = agg @ trans_w + x @ loop_w  (blocks [0, NBX))
//        rel_out = rel_repr @ w_rel          (blocks [NBX, NBX+NBR))
// ---------------------------------------------------------------------------
#define NBX ((NN + 63) / 64)
#define NBR ((NR + 3) / 4)

__global__ void k_gemm(const float* __restrict__ x,
                       const float* __restrict__ wt,
                       const float* __restrict__ wl,
                       const float* __restrict__ rel,
                       const float* __restrict__ wr,
                       float* __restrict__ out,
                       float* __restrict__ out_r) {
    __shared__ __align__(16) float sWt[DD * DD];
    __shared__ __align__(16) float sWl[DD * DD];
    __shared__ float sA[64 * 65];
    __shared__ float sX[64 * 65];

    int tid = threadIdx.x;

    if (blockIdx.x >= NBX) {
        // ---- rel path (reuses sWt as staging) ----
        float(*sR)[DD] = (float(*)[DD])sWt;
        int j = tid & 63, ry = tid >> 6;
        int r0 = (blockIdx.x - NBX) * 4;
        int grow = r0 + ry;
        sR[ry][j] = (grow < NR) ? rel[(size_t)grow * DD + j] : 0.f;
        __syncthreads();
        float acc = 0.f;
#pragma unroll 8
        for (int k = 0; k < DD; k++) acc += sR[ry][k] * __ldg(&wr[k * DD + j]);
        if (grow < NR) out_r[(size_t)grow * DD + j] = acc;
        return;
    }

    for (int j = tid; j < DD * DD; j += 256) { sWt[j] = wt[j]; sWl[j] = wl[j]; }

    int row0 = blockIdx.x * 64;
    {
        int r = tid >> 4;
        int c4 = (tid & 15) * 4;
        for (int rr = r; rr < 64; rr += 16) {
            int grow = row0 + rr;
            float4 a = make_float4(0.f, 0.f, 0.f, 0.f);
            float4 b = make_float4(0.f, 0.f, 0.f, 0.f);
            if (grow < NN) {
                a = *(const float4*)&g_agg[(size_t)grow * DD + c4];
                b = *(const float4*)(x + (size_t)grow * DD + c4);
            }
            float* pa = &sA[rr * 65 + c4];
            float* pb = &sX[rr * 65 + c4];
            pa[0] = a.x; pa[1] = a.y; pa[2] = a.z; pa[3] = a.w;
            pb[0] = b.x; pb[1] = b.y; pb[2] = b.z; pb[3] = b.w;
        }
    }
    __syncthreads();

    int tx = tid & 15;
    int ty = tid >> 4;
    float acc[4][4];
#pragma unroll
    for (int ri = 0; ri < 4; ri++)
#pragma unroll
        for (int cj = 0; cj < 4; cj++) acc[ri][cj] = 0.f;

#pragma unroll 4
    for (int k = 0; k < DD; k++) {
        float4 w0 = *(const float4*)&sWt[k * DD + tx * 4];
        float4 w1 = *(const float4*)&sWl[k * DD + tx * 4];
#pragma unroll
        for (int ri = 0; ri < 4; ri++) {
            float a = sA[(ty * 4 + ri) * 65 + k];
            float b = sX[(ty * 4 + ri) * 65 + k];
            acc[ri][0] += a * w0.x + b * w1.x;
            acc[ri][1] += a * w0.y + b * w1.y;
            acc[ri][2] += a * w0.z + b * w1.z;
            acc[ri][3] += a * w0.w + b * w1.w;
        }
    }

#pragma unroll
    for (int ri = 0; ri < 4; ri++) {
        int grow = row0 + ty * 4 + ri;
        if (grow < NN) {
            float4 v = make_float4(acc[ri][0], acc[ri][1], acc[ri][2], acc[ri][3]);
            *(float4*)(out + (size_t)grow * DD + tx * 4) = v;
        }
    }
}

// ---------------------------------------------------------------------------
extern "C" void kernel_launch(void* const* d_in, const int* in_sizes, int n_in,
                              void* d_out, int out_size) {
    const float* x       = (const float*)d_in[0];
    const float* rel     = (const float*)d_in[1];
    const float* tm      = (const float*)d_in[2];
    const int*   src     = (const int*)d_in[3];
    const int*   dst     = (const int*)d_in[4];
    const int*   ety     = (const int*)d_in[5];
    const int*   eti     = (const int*)d_in[6];
    const float* trans_w = (const float*)d_in[7];
    const float* loop_w  = (const float*)d_in[8];
    const float* w_rel   = (const float*)d_in[9];
    const float* ah      = (const float*)d_in[10];
    const float* at      = (const float*)d_in[11];
    const float* ar      = (const float*)d_in[12];
    const float* ats     = (const float*)d_in[13];

    float* out   = (float*)d_out;            // x_out  [50000*64]
    float* out_r = out + (size_t)NN * DD;    // rel_out [500*64]

    {
        int warps = NN + NR + NT;
        int blocks = (warps * 32 + 255) / 256;
        k_scalar<<<blocks, 256>>>(x, rel, tm, ah, at, ar, ats);
    }

    k_edge1<<<(NE + 255) / 256, 256>>>(src, dst, ety, eti);

    {
        long long threads = (long long)NE * 8;
        int blocks = (int)((threads + 255) / 256);
        k_edge2<<<blocks, 256>>>();
    }

    k_gemm<<<NBX + NBR, 256>>>(x, trans_w, loop_w, rel, w_rel, out, out_r);

    (void)in_sizes; (void)n_in; (void)out_size;
}

// round 6
// speedup vs baseline: 1.7653x; 1.7653x over previous
#include <cuda_runtime.h>
#include <math.h>

#define NN 50000
#define NE 800000
#define DD 64
#define NR 500
#define NT 1000

// ---- scratch (no allocs allowed) ----
__device__ float g_ex[NE];
__device__ float g_den[NN];
__device__ float g_agg[NN * DD];
__device__ float g_hatt[NN];
__device__ float g_tatt[NN];
__device__ float g_ratt[NR];
__device__ float g_tsatt[NT];
__device__ int4  g_pidx[NE];   // {src, dst, etype, etime}

typedef unsigned long long ull;

__device__ __forceinline__ ull ffma2(ull a, ull b, ull c) {
    ull d;
    asm("fma.rn.f32x2 %0, %1, %2, %3;" : "=l"(d) : "l"(a), "l"(b), "l"(c));
    return d;
}
__device__ __forceinline__ ull dup2(float v) {
    ull r;
    asm("mov.b64 %0, {%1, %1};" : "=l"(r) : "f"(v));
    return r;
}
__device__ __forceinline__ float2 unpk(ull v) {
    float2 r;
    asm("mov.b64 {%0, %1}, %2;" : "=f"(r.x), "=f"(r.y) : "l"(v));
    return r;
}

// ---------------------------------------------------------------------------
// Fused: zero agg/den + per-row scalar attention projections (warp per row).
// ---------------------------------------------------------------------------
__global__ void k_scalar(const float* __restrict__ x,
                         const float* __restrict__ rel,
                         const float* __restrict__ tm,
                         const float* __restrict__ ah,
                         const float* __restrict__ at,
                         const float* __restrict__ ar,
                         const float* __restrict__ ats) {
    int gtid = blockIdx.x * blockDim.x + threadIdx.x;
    int stride = gridDim.x * blockDim.x;
    for (int j = gtid; j < NN * DD; j += stride) g_agg[j] = 0.f;
    for (int j = gtid; j < NN; j += stride) g_den[j] = 0.f;

    int w = gtid >> 5;
    int lane = threadIdx.x & 31;
    if (w < NN) {
        const float* row = x + (size_t)w * DD;
        float v0 = row[lane], v1 = row[lane + 32];
        float h = v0 * ah[lane] + v1 * ah[lane + 32];
        float t = v0 * at[lane] + v1 * at[lane + 32];
#pragma unroll
        for (int o = 16; o; o >>= 1) {
            h += __shfl_xor_sync(0xffffffffu, h, o);
            t += __shfl_xor_sync(0xffffffffu, t, o);
        }
        if (lane == 0) { g_hatt[w] = h; g_tatt[w] = t; }
    } else if (w < NN + NR) {
        int r = w - NN;
        const float* row = rel + (size_t)r * DD;
        float s = row[lane] * ar[lane] + row[lane + 32] * ar[lane + 32];
#pragma unroll
        for (int o = 16; o; o >>= 1) s += __shfl_xor_sync(0xffffffffu, s, o);
        if (lane == 0) g_ratt[r] = s;
    } else if (w < NN + NR + NT) {
        int t = w - NN - NR;
        const float* row = tm + (size_t)t * DD;
        float s = row[lane] * ats[lane] + row[lane + 32] * ats[lane + 32];
#pragma unroll
        for (int o = 16; o; o >>= 1) s += __shfl_xor_sync(0xffffffffu, s, o);
        if (lane == 0) g_tsatt[t] = s;
    }
}

// ---------------------------------------------------------------------------
// Edge pass 1: ex = exp(leaky_relu(logit)); den[dst] += ex; pack indices.
// ---------------------------------------------------------------------------
__global__ void k_edge1(const int* __restrict__ src, const int* __restrict__ dst,
                        const int* __restrict__ ety, const int* __restrict__ eti) {
    int i = blockIdx.x * blockDim.x + threadIdx.x;
    if (i >= NE) return;
    int s = src[i], d = dst[i], r = ety[i], t = eti[i];
    g_pidx[i] = make_int4(s, d, r, t);
    float e = g_hatt[s] - g_tatt[d] + g_ratt[r] + g_tsatt[t];
    e = (e > 0.f) ? e : 0.1f * e;
    float ex = __expf(e);
    g_ex[i] = ex;
    atomicAdd(&g_den[d], ex);
}

// ---------------------------------------------------------------------------
// Edge pass 2: 8 threads/edge, 2x float4 per thread (proven R3 fp32 version).
// agg[dst] += att * (x[src]+t) * (rel+t)   via red.global.add.v4.f32
// ---------------------------------------------------------------------------
__global__ void k_edge2(const float* __restrict__ x,
                        const float* __restrict__ rel,
                        const float* __restrict__ tm) {
    int gt = blockIdx.x * blockDim.x + threadIdx.x;
    int i = gt >> 3;
    if (i >= NE) return;
    int sub = gt & 7;
    int c = sub * 4;               // cols [c, c+4) and [c+32, c+36)

    int4 p = __ldg(&g_pidx[i]);    // broadcast across the 8-lane group

    float att = 0.f;
    if (sub == 0) att = __fdividef(__ldg(&g_ex[i]), __ldg(&g_den[p.y]));
    att = __shfl_sync(0xffffffffu, att, (threadIdx.x & 31) & ~7);

    const float* xr = x   + (size_t)p.x * DD;
    const float* rr = rel + (size_t)p.z * DD;
    const float* tr = tm  + (size_t)p.w * DD;

    float4 x0 = *(const float4*)(xr + c);
    float4 x1 = *(const float4*)(xr + c + 32);
    float4 t0 = *(const float4*)(tr + c);
    float4 t1 = *(const float4*)(tr + c + 32);
    float4 r0 = *(const float4*)(rr + c);
    float4 r1 = *(const float4*)(rr + c + 32);

    float4 o0, o1;
    o0.x = (x0.x + t0.x) * (r0.x + t0.x) * att;
    o0.y = (x0.y + t0.y) * (r0.y + t0.y) * att;
    o0.z = (x0.z + t0.z) * (r0.z + t0.z) * att;
    o0.w = (x0.w + t0.w) * (r0.w + t0.w) * att;
    o1.x = (x1.x + t1.x) * (r1.x + t1.x) * att;
    o1.y = (x1.y + t1.y) * (r1.y + t1.y) * att;
    o1.z = (x1.z + t1.z) * (r1.z + t1.z) * att;
    o1.w = (x1.w + t1.w) * (r1.w + t1.w) * att;

    float* pd = &g_agg[(size_t)p.y * DD + c];
    asm volatile("red.global.add.v4.f32 [%0], {%1,%2,%3,%4};"
                 :: "l"(pd), "f"(o0.x), "f"(o0.y), "f"(o0.z), "f"(o0.w)
                 : "memory");
    asm volatile("red.global.add.v4.f32 [%0], {%1,%2,%3,%4};"
                 :: "l"(pd + 32), "f"(o1.x), "f"(o1.y), "f"(o1.z), "f"(o1.w)
                 : "memory");
}

// ---------------------------------------------------------------------------
// Fused GEMM using packed fma.rn.f32x2:
//   blocks [0,NBX):    x_out = agg @ trans_w + x @ loop_w
//   blocks [NBX,+NBR): rel_out = rel_repr @ w_rel
// A/X staged k-major (sAT[k][row]) so row-pairs come from one LDS.64.
// ---------------------------------------------------------------------------
#define NBX ((NN + 63) / 64)
#define NBR ((NR + 3) / 4)

__global__ void k_gemm(const float* __restrict__ x,
                       const float* __restrict__ wt,
                       const float* __restrict__ wl,
                       const float* __restrict__ rel,
                       const float* __restrict__ wr,
                       float* __restrict__ out,
                       float* __restrict__ out_r) {
    __shared__ __align__(16) float sWt[DD * DD];
    __shared__ __align__(16) float sWl[DD * DD];
    __shared__ __align__(16) float sAT[DD * 66];   // [k][row], row-pair aligned
    __shared__ __align__(16) float sXT[DD * 66];

    int tid = threadIdx.x;

    if (blockIdx.x >= NBX) {
        // ---- rel path (reuses sWt as staging) ----
        float(*sR)[DD] = (float(*)[DD])sWt;
        int j = tid & 63, ry = tid >> 6;
        int r0 = (blockIdx.x - NBX) * 4;
        int grow = r0 + ry;
        sR[ry][j] = (grow < NR) ? rel[(size_t)grow * DD + j] : 0.f;
        __syncthreads();
        float acc = 0.f;
#pragma unroll 8
        for (int k = 0; k < DD; k++) acc += sR[ry][k] * __ldg(&wr[k * DD + j]);
        if (grow < NR) out_r[(size_t)grow * DD + j] = acc;
        return;
    }

    for (int j = tid; j < DD * DD; j += 256) { sWt[j] = wt[j]; sWl[j] = wl[j]; }

    int row0 = blockIdx.x * 64;
    {
        int r = tid >> 4;
        int c4 = (tid & 15) * 4;
        for (int rr = r; rr < 64; rr += 16) {
            int grow = row0 + rr;
            float4 a = make_float4(0.f, 0.f, 0.f, 0.f);
            float4 b = make_float4(0.f, 0.f, 0.f, 0.f);
            if (grow < NN) {
                a = *(const float4*)&g_agg[(size_t)grow * DD + c4];
                b = *(const float4*)(x + (size_t)grow * DD + c4);
            }
            sAT[(c4 + 0) * 66 + rr] = a.x;
            sAT[(c4 + 1) * 66 + rr] = a.y;
            sAT[(c4 + 2) * 66 + rr] = a.z;
            sAT[(c4 + 3) * 66 + rr] = a.w;
            sXT[(c4 + 0) * 66 + rr] = b.x;
            sXT[(c4 + 1) * 66 + rr] = b.y;
            sXT[(c4 + 2) * 66 + rr] = b.z;
            sXT[(c4 + 3) * 66 + rr] = b.w;
        }
    }
    __syncthreads();

    int tx = tid & 15;   // column group (4 output cols: tx*4..+3)
    int ty = tid >> 4;   // row group    (4 output rows: ty*4..+3)

    ull acc[4][2];       // [col][row-pair]; pair0 = rows {4ty,4ty+1}
#pragma unroll
    for (int c0 = 0; c0 < 4; c0++) { acc[c0][0] = 0ull; acc[c0][1] = 0ull; }

#pragma unroll 4
    for (int k = 0; k < DD; k++) {
        float4 w0 = *(const float4*)&sWt[k * DD + tx * 4];
        float4 w1 = *(const float4*)&sWl[k * DD + tx * 4];
        ull a01 = *(const ull*)&sAT[k * 66 + ty * 4];
        ull a23 = *(const ull*)&sAT[k * 66 + ty * 4 + 2];
        ull b01 = *(const ull*)&sXT[k * 66 + ty * 4];
        ull b23 = *(const ull*)&sXT[k * 66 + ty * 4 + 2];
        ull d;
        d = dup2(w0.x); acc[0][0] = ffma2(a01, d, acc[0][0]); acc[0][1] = ffma2(a23, d, acc[0][1]);
        d = dup2(w0.y); acc[1][0] = ffma2(a01, d, acc[1][0]); acc[1][1] = ffma2(a23, d, acc[1][1]);
        d = dup2(w0.z); acc[2][0] = ffma2(a01, d, acc[2][0]); acc[2][1] = ffma2(a23, d, acc[2][1]);
        d = dup2(w0.w); acc[3][0] = ffma2(a01, d, acc[3][0]); acc[3][1] = ffma2(a23, d, acc[3][1]);
        d = dup2(w1.x); acc[0][0] = ffma2(b01, d, acc[0][0]); acc[0][1] = ffma2(b23, d, acc[0][1]);
        d = dup2(w1.y); acc[1][0] = ffma2(b01, d, acc[1][0]); acc[1][1] = ffma2(b23, d, acc[1][1]);
        d = dup2(w1.z); acc[2][0] = ffma2(b01, d, acc[2][0]); acc[2][1] = ffma2(b23, d, acc[2][1]);
        d = dup2(w1.w); acc[3][0] = ffma2(b01, d, acc[3][0]); acc[3][1] = ffma2(b23, d, acc[3][1]);
    }

#pragma unroll
    for (int p = 0; p < 2; p++) {
        float2 u0 = unpk(acc[0][p]);
        float2 u1 = unpk(acc[1][p]);
        float2 u2 = unpk(acc[2][p]);
        float2 u3 = unpk(acc[3][p]);
        int rlo = row0 + ty * 4 + p * 2;
        if (rlo < NN)
            *(float4*)(out + (size_t)rlo * DD + tx * 4) =
                make_float4(u0.x, u1.x, u2.x, u3.x);
        if (rlo + 1 < NN)
            *(float4*)(out + (size_t)(rlo + 1) * DD + tx * 4) =
                make_float4(u0.y, u1.y, u2.y, u3.y);
    }
}

// ---------------------------------------------------------------------------
extern "C" void kernel_launch(void* const* d_in, const int* in_sizes, int n_in,
                              void* d_out, int out_size) {
    const float* x       = (const float*)d_in[0];
    const float* rel     = (const float*)d_in[1];
    const float* tm      = (const float*)d_in[2];
    const int*   src     = (const int*)d_in[3];
    const int*   dst     = (const int*)d_in[4];
    const int*   ety     = (const int*)d_in[5];
    const int*   eti     = (const int*)d_in[6];
    const float* trans_w = (const float*)d_in[7];
    const float* loop_w  = (const float*)d_in[8];
    const float* w_rel   = (const float*)d_in[9];
    const float* ah      = (const float*)d_in[10];
    const float* at      = (const float*)d_in[11];
    const float* ar      = (const float*)d_in[12];
    const float* ats     = (const float*)d_in[13];

    float* out   = (float*)d_out;            // x_out  [50000*64]
    float* out_r = out + (size_t)NN * DD;    // rel_out [500*64]

    {
        int warps = NN + NR + NT;
        int blocks = (warps * 32 + 255) / 256;
        k_scalar<<<blocks, 256>>>(x, rel, tm, ah, at, ar, ats);
    }

    k_edge1<<<(NE + 255) / 256, 256>>>(src, dst, ety, eti);

    {
        long long threads = (long long)NE * 8;
        int blocks = (int)((threads + 255) / 256);
        k_edge2<<<blocks, 256>>>(x, rel, tm);
    }

    k_gemm<<<NBX + NBR, 256>>>(x, trans_w, loop_w, rel, w_rel, out, out_r);

    (void)in_sizes; (void)n_in; (void)out_size;
}